// round 3
// baseline (speedup 1.0000x reference)
#include <cuda_runtime.h>

// Inverse 2x2 Haar wavelet reconstruction.
//   ll: (16, 64, 128, 128) f32
//   hf: (16, 192, 128, 128) f32  -> viewed as (16, 64, 3, 128, 128) = lh, hl, hh
//   out:(16, 64, 256, 256) f32
//   out[2h  ][2w  ] = a = ll - lh - hl + hh
//   out[2h  ][2w+1] = b = ll - lh + hl - hh
//   out[2h+1][2w  ] = c = ll + lh - hl - hh
//   out[2h+1][2w+1] = d = ll + lh + hl + hh
//
// Pure memory-bound: 256 MiB read + 256 MiB write, zero reuse -> HBM roofline.
// One thread = one float4 of input width: 4 coalesced LDG.128 + 4 coalesced
// STG.128. Key index identity: hf plane base b*192+3c = 3*(b*64+c) = 3*bc,
// so hf_off = ll_off + 2*bc*plane4 (no b/c split needed at all).

static constexpr int B  = 16;
static constexpr int C  = 64;
static constexpr int H  = 128;
static constexpr int W  = 128;
static constexpr int W4 = W / 4;                               // 32
static constexpr unsigned PLANE4 = (unsigned)H * W4;           // 4096
static constexpr unsigned TOTAL4 = (unsigned)B * C * H * W4;   // 4,194,304 = 16384*256

__global__ __launch_bounds__(256)
void ihaar_kernel(const float4* __restrict__ ll4,
                  const float4* __restrict__ hf4,
                  float4* __restrict__ out4)
{
    // exact grid: 16384 blocks * 256 threads == TOTAL4, no bounds check
    unsigned t = blockIdx.x * 256u + threadIdx.x;

    unsigned w4 = t & (W4 - 1);            // [0,32)
    unsigned r  = t >> 5;                  // (b,c,h) linear = bc*H + h
    unsigned h  = r & (H - 1);
    unsigned bc = r >> 7;                  // b*C + c, [0,1024)

    // ll is laid out bc-major, so t itself IS the ll float4 index.
    unsigned ll_off = t;
    // hf: plane (b*192 + 3c + s) = (3*bc + s); base = 3*bc*PLANE4 + h*W4 + w4
    //   = ll_off + 2*bc*PLANE4
    unsigned hf_off = t + 2u * bc * PLANE4;

    // front-batched loads: MLP = 4, hides DRAM latency
    float4 vll = __ldg(&ll4[ll_off]);
    float4 vlh = __ldg(&hf4[hf_off]);
    float4 vhl = __ldg(&hf4[hf_off + PLANE4]);
    float4 vhh = __ldg(&hf4[hf_off + 2u * PLANE4]);

    // butterfly, 8 adds per lane via shared subexpressions:
    //   p = ll - lh, q = ll + lh, u = hh - hl, v = hh + hl
    //   a = p + u, b = p - u, c = q - v, d = q + v
    float p0 = vll.x - vlh.x, q0 = vll.x + vlh.x;
    float u0 = vhh.x - vhl.x, v0 = vhh.x + vhl.x;
    float p1 = vll.y - vlh.y, q1 = vll.y + vlh.y;
    float u1 = vhh.y - vhl.y, v1 = vhh.y + vhl.y;
    float p2 = vll.z - vlh.z, q2 = vll.z + vlh.z;
    float u2 = vhh.z - vhl.z, v2 = vhh.z + vhl.z;
    float p3 = vll.w - vlh.w, q3 = vll.w + vlh.w;
    float u3 = vhh.w - vhl.w, v3 = vhh.w + vhl.w;

    // output (B, C, 256, 256): rows 2h, 2h+1; cols start at 8*w4.
    // out row = 64 float4 units.
    unsigned orow0 = (bc * (2u * H) + 2u * h) * 64u + 2u * w4;
    unsigned orow1 = orow0 + 64u;

    out4[orow0]     = make_float4(p0 + u0, p0 - u0, p1 + u1, p1 - u1);  // a0 b0 a1 b1
    out4[orow0 + 1] = make_float4(p2 + u2, p2 - u2, p3 + u3, p3 - u3);  // a2 b2 a3 b3
    out4[orow1]     = make_float4(q0 - v0, q0 + v0, q1 - v1, q1 + v1);  // c0 d0 c1 d1
    out4[orow1 + 1] = make_float4(q2 - v2, q2 + v2, q3 - v3, q3 + v3);  // c2 d2 c3 d3
}

extern "C" void kernel_launch(void* const* d_in, const int* in_sizes, int n_in,
                              void* d_out, int out_size)
{
    const float4* ll = (const float4*)d_in[0];
    const float4* hf = (const float4*)d_in[1];
    float4* out = (float4*)d_out;

    ihaar_kernel<<<TOTAL4 / 256u, 256>>>(ll, hf, out);
}